// round 6
// baseline (speedup 1.0000x reference)
#include <cuda_runtime.h>
#include <math.h>
#include <stdint.h>

// Problem constants (fixed shapes from the reference setup)
#define BQ    4
#define NP    16384
#define SQ    2048
#define KNN   32
#define NQTOT (BQ*SQ)          // 8192 query points
#define MROWS (NQTOT*KNN)      // 262144 grouped rows
#define RAD2  0.04f
#define BN_EPS 1e-5f

typedef unsigned long long ULL;

// ---------------- scratch (device globals; no allocations allowed) ----------
__device__ int   g_idx[MROWS];
__device__ float g_h1[(size_t)64*MROWS];    // transposed [C][M]
__device__ float g_h2[(size_t)64*MROWS];    // transposed [C][M]
__device__ float g_h3[(size_t)MROWS*128];   // row-major  [M][C]
__device__ float g_sum[3*128];
__device__ float g_sq[3*128];

// ---------------- packed f32x2 FMA (SASS FFMA2; bit-identical to 2x fmaf) ---
__device__ __forceinline__ void fma2(ULL &d, ULL a, ULL b) {
    asm("fma.rn.f32x2 %0, %1, %2, %0;" : "+l"(d) : "l"(a), "l"(b));
}
__device__ __forceinline__ float2 unpack2(ULL v) {
    float2 r;
    asm("mov.b64 {%0, %1}, %2;" : "=f"(r.x), "=f"(r.y) : "l"(v));
    return r;
}

// ---------------- stats reset (graph replays re-run this) -------------------
__global__ void zero_stats_kernel() {
    int t = threadIdx.x + blockIdx.x * blockDim.x;
    if (t < 3*128) { g_sum[t] = 0.f; g_sq[t] = 0.f; }
}

// ---------------- ball query: warp per query, early exit --------------------
// FROZEN arithmetic: rounding pattern replicates the reference lowering.
__global__ void ballquery_kernel(const float* __restrict__ xyz,
                                 const float* __restrict__ newxyz,
                                 int blockOff) {
    int warp = (((blockIdx.x + blockOff) * blockDim.x) + threadIdx.x) >> 5;
    int lane = threadIdx.x & 31;
    if (warp >= NQTOT) return;
    int b = warp / SQ;
    const float* q = newxyz + (size_t)warp * 3;
    float qx = q[0], qy = q[1], qz = q[2];
    float qq = __fadd_rn(__fadd_rn(__fmul_rn(qx,qx), __fmul_rn(qy,qy)),
                         __fmul_rn(qz,qz));
    const float* xb = xyz + (size_t)b * NP * 3;
    int* outp = g_idx + (size_t)warp * KNN;
    int cnt = 0;
    int first = -1;
    for (int base = 0; base < NP; base += 32) {
        int p = base + lane;
        float x = xb[p*3+0], y = xb[p*3+1], z = xb[p*3+2];
        float xx = __fadd_rn(__fadd_rn(__fmul_rn(x,x), __fmul_rn(y,y)),
                             __fmul_rn(z,z));
        float dt = fmaf(qz, z, fmaf(qy, y, __fmul_rn(qx, x)));
        float d2 = __fsub_rn(__fadd_rn(qq, xx), __fmul_rn(2.0f, dt));
        bool hit = !(d2 > RAD2);
        unsigned mask = __ballot_sync(0xffffffffu, hit);
        if (mask) {
            if (first < 0) first = base + __ffs(mask) - 1;
            int pos = cnt + __popc(mask & ((1u << lane) - 1u));
            if (hit && pos < KNN) outp[pos] = p;
            cnt += __popc(mask);
            if (cnt >= KNN) break;
        }
    }
    if (cnt < KNN) {
        if (first < 0) first = 0;
        for (int pos = cnt + lane; pos < KNN; pos += 32) outp[pos] = first;
    }
}

// ---------------- f32x2 GEMM core: 128 rows x 64 cols per block -------------
// Xs: [CIN+1][128] floats (extra row = branch-free prefetch).
// Wd: [CIN+1][64] float2 pre-duplicated (w,w); row stride 512 B.
// Warp w owns cols 8w..8w+7 = 64 contiguous bytes at byte offset 0/16/32/48.
// Software-pipelined: prefetch c+1 operands during c's FMAs.
template<int CIN>
__device__ __forceinline__ void gemm_core(const float* Xs, const float2* Wd,
                                          ULL acc[2][8], int lane, int cb)
{
    const float* xp = Xs + 4*lane;
    const char* wp = reinterpret_cast<const char*>(Wd + cb);
    ulonglong2 xa = *reinterpret_cast<const ulonglong2*>(xp);
    ulonglong2 w0 = *reinterpret_cast<const ulonglong2*>(wp);
    ulonglong2 w1 = *reinterpret_cast<const ulonglong2*>(wp + 16);
    #pragma unroll 4
    for (int c = 0; c < CIN; c++) {
        // prefetch rest of this k-step + first half of next (row CIN exists)
        ulonglong2 xn  = *reinterpret_cast<const ulonglong2*>(xp + (c+1)*128);
        ulonglong2 w2  = *reinterpret_cast<const ulonglong2*>(wp + c*512 + 32);
        ulonglong2 w3  = *reinterpret_cast<const ulonglong2*>(wp + c*512 + 48);
        ulonglong2 w0n = *reinterpret_cast<const ulonglong2*>(wp + (c+1)*512);
        ulonglong2 w1n = *reinterpret_cast<const ulonglong2*>(wp + (c+1)*512 + 16);
        fma2(acc[0][0], xa.x, w0.x); fma2(acc[1][0], xa.y, w0.x);
        fma2(acc[0][1], xa.x, w0.y); fma2(acc[1][1], xa.y, w0.y);
        fma2(acc[0][2], xa.x, w1.x); fma2(acc[1][2], xa.y, w1.x);
        fma2(acc[0][3], xa.x, w1.y); fma2(acc[1][3], xa.y, w1.y);
        fma2(acc[0][4], xa.x, w2.x); fma2(acc[1][4], xa.y, w2.x);
        fma2(acc[0][5], xa.x, w2.y); fma2(acc[1][5], xa.y, w2.y);
        fma2(acc[0][6], xa.x, w3.x); fma2(acc[1][6], xa.y, w3.x);
        fma2(acc[0][7], xa.x, w3.y); fma2(acc[1][7], xa.y, w3.y);
        xa = xn; w0 = w0n; w1 = w1n;
    }
}

// Epilogue. TRANS=true: Y is [C][MROWS] channel-major. Else row-major [M][COUTfull].
template<bool TRANS>
__device__ __forceinline__ void gemm_epilogue(
    ULL acc[2][8], int m0, int lane, int cb, int t, int nOff, int COUTfull,
    const float* __restrict__ bias, float* __restrict__ Y,
    float* s_sum, float* s_sq,
    float* __restrict__ gsum, float* __restrict__ gsq)
{
    float colSum[8], colSq[8], bv[8];
    #pragma unroll
    for (int j = 0; j < 8; j++) { colSum[j] = 0.f; colSq[j] = 0.f; bv[j] = bias[cb + j]; }

    if (TRANS) {
        #pragma unroll
        for (int j = 0; j < 8; j++) {
            float2 u0 = unpack2(acc[0][j]);
            float2 u1 = unpack2(acc[1][j]);
            float v0 = u0.x + bv[j], v1 = u0.y + bv[j];
            float v2 = u1.x + bv[j], v3 = u1.y + bv[j];
            colSum[j] = (v0+v1)+(v2+v3);
            float sq = 0.f;
            sq = fmaf(v0,v0,sq); sq = fmaf(v1,v1,sq);
            sq = fmaf(v2,v2,sq); sq = fmaf(v3,v3,sq);
            colSq[j] = sq;
            float* basep = Y + (size_t)(nOff + cb + j) * MROWS + m0;
            *reinterpret_cast<float4*>(basep + 4*lane) = make_float4(v0, v1, v2, v3);
        }
    } else {
        #pragma unroll
        for (int p = 0; p < 2; p++) {
            float vlo[8], vhi[8];
            #pragma unroll
            for (int j = 0; j < 8; j++) {
                float2 v = unpack2(acc[p][j]);
                float a = v.x + bv[j], b = v.y + bv[j];
                vlo[j] = a; vhi[j] = b;
                colSum[j] += a + b;
                colSq[j] = fmaf(a, a, colSq[j]);
                colSq[j] = fmaf(b, b, colSq[j]);
            }
            int r0 = 4*lane + 2*p;
            float* d0 = Y + (size_t)(m0 + r0) * COUTfull + nOff + cb;
            float* d1 = d0 + COUTfull;
            *reinterpret_cast<float4*>(d0)     = make_float4(vlo[0], vlo[1], vlo[2], vlo[3]);
            *reinterpret_cast<float4*>(d0 + 4) = make_float4(vlo[4], vlo[5], vlo[6], vlo[7]);
            *reinterpret_cast<float4*>(d1)     = make_float4(vhi[0], vhi[1], vhi[2], vhi[3]);
            *reinterpret_cast<float4*>(d1 + 4) = make_float4(vhi[4], vhi[5], vhi[6], vhi[7]);
        }
    }
    #pragma unroll
    for (int j = 0; j < 8; j++) {
        atomicAdd(&s_sum[cb + j], colSum[j]);
        atomicAdd(&s_sq[cb + j],  colSq[j]);
    }
    __syncthreads();
    if (t < 64) {
        atomicAdd(&gsum[nOff + t], s_sum[t]);
        atomicAdd(&gsq[nOff + t],  s_sq[t]);
    }
}

// ---------------- layer 1: gather (ballquery idx) + GEMM 67->64 -------------
__global__ void __launch_bounds__(256, 3)
gemm1_kernel(const float* __restrict__ xyz,
             const float* __restrict__ points,
             const float* __restrict__ newxyz,
             const float* __restrict__ W,     // [64][67]
             const float* __restrict__ bias,
             float* __restrict__ Yt,          // [64][MROWS]
             float* __restrict__ gsum,
             float* __restrict__ gsq)
{
    constexpr int CIN = 67;
    extern __shared__ float sm[];
    float*  Xs    = sm;                                            // [68][128]
    float2* Wd    = reinterpret_cast<float2*>(sm + (CIN+1)*128);   // [68][64] dup
    float*  s_sum = reinterpret_cast<float*>(Wd + (CIN+1)*64);
    float*  s_sq  = s_sum + 64;
    const int t    = threadIdx.x;
    const int lane = t & 31;
    const int warp = t >> 5;
    const int cb   = warp * 8;
    const int m0   = blockIdx.x * 128;

    for (int i = t; i < 64*CIN; i += 256) {
        int o = i / CIN, c = i - o*CIN;
        float w = W[i];
        Wd[c*64 + o] = make_float2(w, w);
    }
    if (t < 64) { s_sum[t] = 0.f; s_sq[t] = 0.f; }

    {   // gather: two threads per row (random j -> inherently scattered)
        const int r = t >> 1;
        const int h = t & 1;
        const int m = m0 + r;
        const int b = m >> 16;
        const int s = (m >> 5) & (SQ - 1);
        const int j = g_idx[m];
        const float4* prow =
            reinterpret_cast<const float4*>(points + (size_t)(b*NP + j) * 64) + h*8;
        #pragma unroll
        for (int v = 0; v < 8; v++) {
            float4 x = prow[v];
            int c = 3 + h*32 + v*4;
            Xs[(c+0)*128 + r] = x.x;
            Xs[(c+1)*128 + r] = x.y;
            Xs[(c+2)*128 + r] = x.z;
            Xs[(c+3)*128 + r] = x.w;
        }
        if (h == 0) {
            const float* pj = xyz    + (size_t)(b*NP + j) * 3;
            const float* qv = newxyz + (size_t)(b*SQ + s) * 3;
            Xs[0*128 + r] = pj[0] - qv[0];
            Xs[1*128 + r] = pj[1] - qv[1];
            Xs[2*128 + r] = pj[2] - qv[2];
        }
    }
    __syncthreads();

    ULL acc[2][8];
    #pragma unroll
    for (int p = 0; p < 2; p++)
        #pragma unroll
        for (int j = 0; j < 8; j++) acc[p][j] = 0ull;

    gemm_core<CIN>(Xs, Wd, acc, lane, cb);
    gemm_epilogue<true>(acc, m0, lane, cb, t, 0, 64, bias, Yt, s_sum, s_sq, gsum, gsq);
}

// ---------------- layers 2/3: BN+ReLU(prev) folded, transposed input --------
template<bool TRANS>
__global__ void __launch_bounds__(256, 3)
gemm_bn_kernel(const float* __restrict__ Xt,   // [64][MROWS]
               const float* __restrict__ W,    // [COUTtot][64]
               const float* __restrict__ bias,
               const float* __restrict__ gammaP,
               const float* __restrict__ betaP,
               const float* __restrict__ gsumP,
               const float* __restrict__ gsqP,
               float* __restrict__ Y,
               int COUTfull,
               float* __restrict__ gsum,
               float* __restrict__ gsq)
{
    constexpr int CIN = 64;
    extern __shared__ float sm[];
    float*  Xs    = sm;                                            // [65][128]
    float2* Wd    = reinterpret_cast<float2*>(sm + (CIN+1)*128);   // [65][64] dup
    float*  s_sum = reinterpret_cast<float*>(Wd + (CIN+1)*64);
    float*  s_sq  = s_sum + 64;
    float*  sscl  = s_sq + 64;
    float*  sshf  = sscl + 64;
    const int t    = threadIdx.x;
    const int lane = t & 31;
    const int warp = t >> 5;
    const int cb   = warp * 8;
    const int m0   = blockIdx.x * 128;
    const int nOff = blockIdx.y * 64;

    const float* Wblk = W + (size_t)nOff * CIN;
    for (int i = t; i < 64*CIN; i += 256) {
        int o = i >> 6, c = i & 63;
        float w = Wblk[i];
        Wd[c*64 + o] = make_float2(w, w);
    }
    if (t < 64) {
        s_sum[t] = 0.f; s_sq[t] = 0.f;
        // inline finalize of previous layer's BN (identical arithmetic)
        const float invM = 1.0f / (float)MROWS;
        float mean = gsumP[t] * invM;
        float var  = gsqP[t] * invM - mean*mean;
        float rs = rsqrtf(var + BN_EPS);
        float sc = gammaP[t] * rs;
        sscl[t] = sc;
        sshf[t] = betaP[t] - mean*sc;
    }
    __syncthreads();

    {   // coalesced transposed load + BN + ReLU: 4 threads per channel
        const int c  = t >> 2;          // 0..63
        const int q4 = (t & 3) * 32;    // 0..96
        float sc = sscl[c], sh = sshf[c];
        const float4* src = reinterpret_cast<const float4*>(
            Xt + (size_t)c*MROWS + m0 + q4);
        float4* dst = reinterpret_cast<float4*>(Xs + c*128 + q4);
        #pragma unroll
        for (int v = 0; v < 8; v++) {
            float4 x = src[v];
            float4 o;
            o.x = fmaxf(fmaf(x.x, sc, sh), 0.f);
            o.y = fmaxf(fmaf(x.y, sc, sh), 0.f);
            o.z = fmaxf(fmaf(x.z, sc, sh), 0.f);
            o.w = fmaxf(fmaf(x.w, sc, sh), 0.f);
            dst[v] = o;
        }
    }
    __syncthreads();

    ULL acc[2][8];
    #pragma unroll
    for (int p = 0; p < 2; p++)
        #pragma unroll
        for (int j = 0; j < 8; j++) acc[p][j] = 0ull;

    gemm_core<CIN>(Xs, Wd, acc, lane, cb);
    gemm_epilogue<TRANS>(acc, m0, lane, cb, t, nOff, COUTfull,
                         bias + nOff, Y, s_sum, s_sq, gsum, gsq);
}

// ---------------- BN3 + ReLU + max over K + transpose -----------------------
__global__ void maxpool_kernel(const float* __restrict__ gamma,
                               const float* __restrict__ beta,
                               float* __restrict__ out)
{
    const int q = blockIdx.x;      // b*SQ + s
    const int o = threadIdx.x;     // channel 0..127
    const int b = q / SQ, s = q - b*SQ;
    const float invM = 1.0f / (float)MROWS;
    float mean = g_sum[2*128 + o] * invM;
    float var  = g_sq[2*128 + o] * invM - mean*mean;
    float rs = rsqrtf(var + BN_EPS);
    float sc = gamma[o] * rs;
    float sh = beta[o] - mean*sc;
    const float* h = g_h3 + (size_t)q * KNN * 128 + o;
    float mx = -3.402823466e38f;
    #pragma unroll
    for (int k = 0; k < KNN; k++)
        mx = fmaxf(mx, fmaf(h[(size_t)k*128], sc, sh));
    out[(size_t)(b*128 + o) * SQ + s] = fmaxf(mx, 0.f);
}

// ---------------- launch ------------------------------------------------
extern "C" void kernel_launch(void* const* d_in, const int* in_sizes, int n_in,
                              void* d_out, int out_size) {
    const float* xyz    = (const float*)d_in[0];
    const float* points = (const float*)d_in[1];
    const float* newxyz = (const float*)d_in[2];
    const float* W1 = (const float*)d_in[3],  *b1 = (const float*)d_in[4];
    const float* ga1 = (const float*)d_in[5], *be1 = (const float*)d_in[6];
    const float* W2 = (const float*)d_in[7],  *b2 = (const float*)d_in[8];
    const float* ga2 = (const float*)d_in[9], *be2 = (const float*)d_in[10];
    const float* W3 = (const float*)d_in[11], *b3 = (const float*)d_in[12];
    const float* ga3 = (const float*)d_in[13], *be3 = (const float*)d_in[14];

    float* out = (float*)d_out;
    float* outPts = out;
    if (out_size == BQ*SQ*3 + BQ*128*SQ) {
        cudaMemcpyAsync(out, newxyz, sizeof(float)*BQ*SQ*3, cudaMemcpyDeviceToDevice);
        outPts = out + BQ*SQ*3;
    }

    float *h1, *h2, *h3, *gsum, *gsq;
    cudaGetSymbolAddress((void**)&h1, g_h1);
    cudaGetSymbolAddress((void**)&h2, g_h2);
    cudaGetSymbolAddress((void**)&h3, g_h3);
    cudaGetSymbolAddress((void**)&gsum, g_sum);
    cudaGetSymbolAddress((void**)&gsq, g_sq);

    const int smem1 = 68*128*4 + 68*64*8 + 2*64*4;    // 70,144 B  -> 3 CTAs/SM
    const int smem2 = 65*128*4 + 65*64*8 + 4*64*4;    // 67,584 B  -> 3 CTAs/SM
    cudaFuncSetAttribute(gemm1_kernel, cudaFuncAttributeMaxDynamicSharedMemorySize, smem1);
    cudaFuncSetAttribute(gemm_bn_kernel<true>,  cudaFuncAttributeMaxDynamicSharedMemorySize, smem2);
    cudaFuncSetAttribute(gemm_bn_kernel<false>, cudaFuncAttributeMaxDynamicSharedMemorySize, smem2);

    // Launch order fixed so ncu (-s 5 -c 1) profiles launch #6 = layer-3 GEMM.
    zero_stats_kernel<<<1, 512>>>();                                   // 1
    ballquery_kernel<<<512, 256>>>(xyz, newxyz, 0);                    // 2
    ballquery_kernel<<<512, 256>>>(xyz, newxyz, 512);                  // 3

    gemm1_kernel<<<MROWS/128, 256, smem1>>>(xyz, points, newxyz, W1, b1,
                                            h1, gsum + 0, gsq + 0);    // 4

    gemm_bn_kernel<true><<<dim3(MROWS/128, 1), 256, smem2>>>(
        h1, W2, b2, ga1, be1, gsum + 0, gsq + 0,
        h2, 64, gsum + 128, gsq + 128);                                // 5

    gemm_bn_kernel<false><<<dim3(MROWS/128, 2), 256, smem2>>>(
        h2, W3, b3, ga2, be2, gsum + 128, gsq + 128,
        h3, 128, gsum + 256, gsq + 256);                               // 6 (profiled)

    maxpool_kernel<<<NQTOT, 128>>>(ga3, be3, outPts);                  // 7
}

// round 7
// speedup vs baseline: 1.2352x; 1.2352x over previous
#include <cuda_runtime.h>
#include <math.h>
#include <stdint.h>

// Problem constants (fixed shapes from the reference setup)
#define BQ    4
#define NP    16384
#define SQ    2048
#define KNN   32
#define NQTOT (BQ*SQ)          // 8192 query points
#define MROWS (NQTOT*KNN)      // 262144 grouped rows
#define RAD2  0.04f
#define BN_EPS 1e-5f
#define XSTR  132              // padded smem row stride (floats)

typedef unsigned long long ULL;

// ---------------- scratch (device globals; no allocations allowed) ----------
__device__ int   g_idx[MROWS];
__device__ float g_h1[(size_t)64*MROWS];    // transposed [C][M]
__device__ float g_h2[(size_t)64*MROWS];    // transposed [C][M]
__device__ float g_h3[(size_t)MROWS*128];   // row-major  [M][C]
__device__ float g_sum[3*128];
__device__ float g_sq[3*128];

// ---------------- packed f32x2 helpers (bit-identical to 2x fmaf) -----------
__device__ __forceinline__ void fma2(ULL &d, ULL a, ULL b) {
    asm("fma.rn.f32x2 %0, %1, %2, %0;" : "+l"(d) : "l"(a), "l"(b));
}
__device__ __forceinline__ ULL pack2(float x) {
    ULL r;
    asm("mov.b64 %0, {%1, %1};" : "=l"(r) : "f"(x));
    return r;
}
__device__ __forceinline__ float2 unpack2(ULL v) {
    float2 r;
    asm("mov.b64 {%0, %1}, %2;" : "=f"(r.x), "=f"(r.y) : "l"(v));
    return r;
}

// ---------------- stats reset (graph replays re-run this) -------------------
__global__ void zero_stats_kernel() {
    int t = threadIdx.x + blockIdx.x * blockDim.x;
    if (t < 3*128) { g_sum[t] = 0.f; g_sq[t] = 0.f; }
}

// ---------------- ball query: warp per query, early exit --------------------
// FROZEN arithmetic: rounding pattern replicates the reference lowering.
__global__ void ballquery_kernel(const float* __restrict__ xyz,
                                 const float* __restrict__ newxyz,
                                 int blockOff) {
    int warp = (((blockIdx.x + blockOff) * blockDim.x) + threadIdx.x) >> 5;
    int lane = threadIdx.x & 31;
    if (warp >= NQTOT) return;
    int b = warp / SQ;
    const float* q = newxyz + (size_t)warp * 3;
    float qx = q[0], qy = q[1], qz = q[2];
    float qq = __fadd_rn(__fadd_rn(__fmul_rn(qx,qx), __fmul_rn(qy,qy)),
                         __fmul_rn(qz,qz));
    const float* xb = xyz + (size_t)b * NP * 3;
    int* outp = g_idx + (size_t)warp * KNN;
    int cnt = 0;
    int first = -1;
    for (int base = 0; base < NP; base += 32) {
        int p = base + lane;
        float x = xb[p*3+0], y = xb[p*3+1], z = xb[p*3+2];
        float xx = __fadd_rn(__fadd_rn(__fmul_rn(x,x), __fmul_rn(y,y)),
                             __fmul_rn(z,z));
        float dt = fmaf(qz, z, fmaf(qy, y, __fmul_rn(qx, x)));
        float d2 = __fsub_rn(__fadd_rn(qq, xx), __fmul_rn(2.0f, dt));
        bool hit = !(d2 > RAD2);
        unsigned mask = __ballot_sync(0xffffffffu, hit);
        if (mask) {
            if (first < 0) first = base + __ffs(mask) - 1;
            int pos = cnt + __popc(mask & ((1u << lane) - 1u));
            if (hit && pos < KNN) outp[pos] = p;
            cnt += __popc(mask);
            if (cnt >= KNN) break;
        }
    }
    if (cnt < KNN) {
        if (first < 0) first = 0;
        for (int pos = cnt + lane; pos < KNN; pos += 32) outp[pos] = first;
    }
}

// ---------------- f32x2 GEMM core: 128 rows x 64 cols per block -------------
// Xs: [CIN][XSTR] floats. Ws: [CIN][64] floats (NOT duplicated).
// Warp w owns cols 8w..8w+7. Lane owns rows 4l..4l+3 (one LDS.128 per k).
// B-operand = natural (w_j, w_j+1) float2 pairs; A-operand = (x,x) reg packs.
template<int CIN>
__device__ __forceinline__ void gemm_core(const float* Xs, const float* Ws,
                                          ULL acc[4][4], int lane, int cb)
{
    const float* xp = Xs + 4*lane;
    const float* wp = Ws + cb;
    #pragma unroll 4
    for (int c = 0; c < CIN; c++) {
        float4 xv = *reinterpret_cast<const float4*>(xp + c*XSTR);
        ulonglong2 wa = *reinterpret_cast<const ulonglong2*>(wp + c*64);
        ulonglong2 wb = *reinterpret_cast<const ulonglong2*>(wp + c*64 + 4);
        ULL x0 = pack2(xv.x), x1 = pack2(xv.y);
        ULL x2 = pack2(xv.z), x3 = pack2(xv.w);
        fma2(acc[0][0], x0, wa.x); fma2(acc[0][1], x0, wa.y);
        fma2(acc[0][2], x0, wb.x); fma2(acc[0][3], x0, wb.y);
        fma2(acc[1][0], x1, wa.x); fma2(acc[1][1], x1, wa.y);
        fma2(acc[1][2], x1, wb.x); fma2(acc[1][3], x1, wb.y);
        fma2(acc[2][0], x2, wa.x); fma2(acc[2][1], x2, wa.y);
        fma2(acc[2][2], x2, wb.x); fma2(acc[2][3], x2, wb.y);
        fma2(acc[3][0], x3, wa.x); fma2(acc[3][1], x3, wa.y);
        fma2(acc[3][2], x3, wb.x); fma2(acc[3][3], x3, wb.y);
    }
}

// Epilogue. acc[r][j] holds (col cb+2j, col cb+2j+1) for row m0+4*lane+r.
// TRANS=true: Y is [C][MROWS] channel-major. Else row-major [M][COUTfull].
template<bool TRANS>
__device__ __forceinline__ void gemm_epilogue(
    ULL acc[4][4], int m0, int lane, int cb, int t, int nOff, int COUTfull,
    const float* __restrict__ bias, float* __restrict__ Y,
    float* s_sum, float* s_sq,
    float* __restrict__ gsum, float* __restrict__ gsq)
{
    float colSum[8], colSq[8], bv[8];
    #pragma unroll
    for (int jj = 0; jj < 8; jj++) { colSum[jj] = 0.f; colSq[jj] = 0.f; bv[jj] = bias[cb + jj]; }

    if (TRANS) {
        #pragma unroll
        for (int j = 0; j < 4; j++) {
            float2 a0 = unpack2(acc[0][j]);
            float2 a1 = unpack2(acc[1][j]);
            float2 a2 = unpack2(acc[2][j]);
            float2 a3 = unpack2(acc[3][j]);
            {   // column cb + 2j
                int jj = 2*j;
                float v0 = a0.x + bv[jj], v1 = a1.x + bv[jj];
                float v2 = a2.x + bv[jj], v3 = a3.x + bv[jj];
                colSum[jj] = (v0+v1)+(v2+v3);
                float sq = 0.f;
                sq = fmaf(v0,v0,sq); sq = fmaf(v1,v1,sq);
                sq = fmaf(v2,v2,sq); sq = fmaf(v3,v3,sq);
                colSq[jj] = sq;
                float* basep = Y + (size_t)(nOff + cb + jj) * MROWS + m0;
                *reinterpret_cast<float4*>(basep + 4*lane) = make_float4(v0, v1, v2, v3);
            }
            {   // column cb + 2j + 1
                int jj = 2*j + 1;
                float v0 = a0.y + bv[jj], v1 = a1.y + bv[jj];
                float v2 = a2.y + bv[jj], v3 = a3.y + bv[jj];
                colSum[jj] = (v0+v1)+(v2+v3);
                float sq = 0.f;
                sq = fmaf(v0,v0,sq); sq = fmaf(v1,v1,sq);
                sq = fmaf(v2,v2,sq); sq = fmaf(v3,v3,sq);
                colSq[jj] = sq;
                float* basep = Y + (size_t)(nOff + cb + jj) * MROWS + m0;
                *reinterpret_cast<float4*>(basep + 4*lane) = make_float4(v0, v1, v2, v3);
            }
        }
    } else {
        #pragma unroll
        for (int r = 0; r < 4; r++) {
            float vals[8];
            #pragma unroll
            for (int j = 0; j < 4; j++) {
                float2 v = unpack2(acc[r][j]);
                float a = v.x + bv[2*j], b = v.y + bv[2*j+1];
                vals[2*j] = a; vals[2*j+1] = b;
                colSum[2*j]   += a;
                colSum[2*j+1] += b;
                colSq[2*j]    = fmaf(a, a, colSq[2*j]);
                colSq[2*j+1]  = fmaf(b, b, colSq[2*j+1]);
            }
            float* d0 = Y + (size_t)(m0 + 4*lane + r) * COUTfull + nOff + cb;
            *reinterpret_cast<float4*>(d0)     = make_float4(vals[0], vals[1], vals[2], vals[3]);
            *reinterpret_cast<float4*>(d0 + 4) = make_float4(vals[4], vals[5], vals[6], vals[7]);
        }
    }
    #pragma unroll
    for (int jj = 0; jj < 8; jj++) {
        atomicAdd(&s_sum[cb + jj], colSum[jj]);
        atomicAdd(&s_sq[cb + jj],  colSq[jj]);
    }
    __syncthreads();
    if (t < 64) {
        atomicAdd(&gsum[nOff + t], s_sum[t]);
        atomicAdd(&gsq[nOff + t],  s_sq[t]);
    }
}

// ---------------- layer 1: gather (ballquery idx) + GEMM 67->64 -------------
__global__ void __launch_bounds__(256, 4)
gemm1_kernel(const float* __restrict__ xyz,
             const float* __restrict__ points,
             const float* __restrict__ newxyz,
             const float* __restrict__ W,     // [64][67]
             const float* __restrict__ bias,
             float* __restrict__ Yt,          // [64][MROWS]
             float* __restrict__ gsum,
             float* __restrict__ gsq)
{
    constexpr int CIN = 67;
    extern __shared__ float sm[];
    float* Xs    = sm;                       // [67][XSTR]
    float* Ws    = sm + CIN*XSTR;            // [67][64]
    float* s_sum = Ws + CIN*64;
    float* s_sq  = s_sum + 64;
    const int t    = threadIdx.x;
    const int lane = t & 31;
    const int warp = t >> 5;
    const int cb   = warp * 8;
    const int m0   = blockIdx.x * 128;

    for (int i = t; i < 64*CIN; i += 256) {
        int o = i / CIN, c = i - o*CIN;
        Ws[c*64 + o] = W[i];
    }
    if (t < 64) { s_sum[t] = 0.f; s_sq[t] = 0.f; }

    {   // coalesced gather: 16 lanes cover 16 consecutive 16B chunks of a row
        const int k = t & 15;                // chunk 0..15 (channels 3+4k..6+4k)
        const int rb = t >> 4;               // 0..15
        #pragma unroll
        for (int it = 0; it < 8; it++) {
            const int r = rb + it*16;
            const int m = m0 + r;
            const int b = m >> 16;
            const int j = g_idx[m];
            float4 x = *(reinterpret_cast<const float4*>(
                             points + (size_t)(b*NP + j) * 64) + k);
            const int c = 3 + 4*k;
            Xs[(c+0)*XSTR + r] = x.x;
            Xs[(c+1)*XSTR + r] = x.y;
            Xs[(c+2)*XSTR + r] = x.z;
            Xs[(c+3)*XSTR + r] = x.w;
            if (k == 0) {
                const int s = (m >> 5) & (SQ - 1);
                const float* pj = xyz    + (size_t)(b*NP + j) * 3;
                const float* qv = newxyz + (size_t)(b*SQ + s) * 3;
                Xs[0*XSTR + r] = pj[0] - qv[0];
                Xs[1*XSTR + r] = pj[1] - qv[1];
                Xs[2*XSTR + r] = pj[2] - qv[2];
            }
        }
    }
    __syncthreads();

    ULL acc[4][4];
    #pragma unroll
    for (int p = 0; p < 4; p++)
        #pragma unroll
        for (int j = 0; j < 4; j++) acc[p][j] = 0ull;

    gemm_core<CIN>(Xs, Ws, acc, lane, cb);
    gemm_epilogue<true>(acc, m0, lane, cb, t, 0, 64, bias, Yt, s_sum, s_sq, gsum, gsq);
}

// ---------------- layers 2/3: BN+ReLU(prev) folded, transposed input --------
template<bool TRANS>
__global__ void __launch_bounds__(256, 4)
gemm_bn_kernel(const float* __restrict__ Xt,   // [64][MROWS]
               const float* __restrict__ W,    // [COUTtot][64]
               const float* __restrict__ bias,
               const float* __restrict__ gammaP,
               const float* __restrict__ betaP,
               const float* __restrict__ gsumP,
               const float* __restrict__ gsqP,
               float* __restrict__ Y,
               int COUTfull,
               float* __restrict__ gsum,
               float* __restrict__ gsq)
{
    constexpr int CIN = 64;
    extern __shared__ float sm[];
    float* Xs    = sm;                       // [64][XSTR]
    float* Ws    = sm + CIN*XSTR;            // [64][64]
    float* s_sum = Ws + CIN*64;
    float* s_sq  = s_sum + 64;
    float* sscl  = s_sq + 64;
    float* sshf  = sscl + 64;
    const int t    = threadIdx.x;
    const int lane = t & 31;
    const int warp = t >> 5;
    const int cb   = warp * 8;
    const int m0   = blockIdx.x * 128;
    const int nOff = blockIdx.y * 64;

    const float* Wblk = W + (size_t)nOff * CIN;
    for (int i = t; i < 64*CIN; i += 256) {
        int o = i >> 6, c = i & 63;
        Ws[c*64 + o] = Wblk[i];
    }
    if (t < 64) {
        s_sum[t] = 0.f; s_sq[t] = 0.f;
        // inline finalize of previous layer's BN (identical arithmetic)
        const float invM = 1.0f / (float)MROWS;
        float mean = gsumP[t] * invM;
        float var  = gsqP[t] * invM - mean*mean;
        float rs = rsqrtf(var + BN_EPS);
        float sc = gammaP[t] * rs;
        sscl[t] = sc;
        sshf[t] = betaP[t] - mean*sc;
    }
    __syncthreads();

    {   // warp-per-channel contiguous load (512B/instr) + BN + ReLU
        #pragma unroll
        for (int i = 0; i < 8; i++) {
            const int c = warp*8 + i;
            const float sc = sscl[c], sh = sshf[c];
            float4 x = *reinterpret_cast<const float4*>(
                Xt + (size_t)c*MROWS + m0 + 4*lane);
            float4 o;
            o.x = fmaxf(fmaf(x.x, sc, sh), 0.f);
            o.y = fmaxf(fmaf(x.y, sc, sh), 0.f);
            o.z = fmaxf(fmaf(x.z, sc, sh), 0.f);
            o.w = fmaxf(fmaf(x.w, sc, sh), 0.f);
            *reinterpret_cast<float4*>(Xs + c*XSTR + 4*lane) = o;
        }
    }
    __syncthreads();

    ULL acc[4][4];
    #pragma unroll
    for (int p = 0; p < 4; p++)
        #pragma unroll
        for (int j = 0; j < 4; j++) acc[p][j] = 0ull;

    gemm_core<CIN>(Xs, Ws, acc, lane, cb);
    gemm_epilogue<TRANS>(acc, m0, lane, cb, t, nOff, COUTfull,
                         bias + nOff, Y, s_sum, s_sq, gsum, gsq);
}

// ---------------- BN3 + ReLU + max over K + transpose -----------------------
__global__ void maxpool_kernel(const float* __restrict__ gamma,
                               const float* __restrict__ beta,
                               float* __restrict__ out)
{
    const int q = blockIdx.x;      // b*SQ + s
    const int o = threadIdx.x;     // channel 0..127
    const int b = q / SQ, s = q - b*SQ;
    const float invM = 1.0f / (float)MROWS;
    float mean = g_sum[2*128 + o] * invM;
    float var  = g_sq[2*128 + o] * invM - mean*mean;
    float rs = rsqrtf(var + BN_EPS);
    float sc = gamma[o] * rs;
    float sh = beta[o] - mean*sc;
    const float* h = g_h3 + (size_t)q * KNN * 128 + o;
    float mx = -3.402823466e38f;
    #pragma unroll
    for (int k = 0; k < KNN; k++)
        mx = fmaxf(mx, fmaf(h[(size_t)k*128], sc, sh));
    out[(size_t)(b*128 + o) * SQ + s] = fmaxf(mx, 0.f);
}

// ---------------- launch ------------------------------------------------
extern "C" void kernel_launch(void* const* d_in, const int* in_sizes, int n_in,
                              void* d_out, int out_size) {
    const float* xyz    = (const float*)d_in[0];
    const float* points = (const float*)d_in[1];
    const float* newxyz = (const float*)d_in[2];
    const float* W1 = (const float*)d_in[3],  *b1 = (const float*)d_in[4];
    const float* ga1 = (const float*)d_in[5], *be1 = (const float*)d_in[6];
    const float* W2 = (const float*)d_in[7],  *b2 = (const float*)d_in[8];
    const float* ga2 = (const float*)d_in[9], *be2 = (const float*)d_in[10];
    const float* W3 = (const float*)d_in[11], *b3 = (const float*)d_in[12];
    const float* ga3 = (const float*)d_in[13], *be3 = (const float*)d_in[14];

    float* out = (float*)d_out;
    float* outPts = out;
    if (out_size == BQ*SQ*3 + BQ*128*SQ) {
        cudaMemcpyAsync(out, newxyz, sizeof(float)*BQ*SQ*3, cudaMemcpyDeviceToDevice);
        outPts = out + BQ*SQ*3;
    }

    float *h1, *h2, *h3, *gsum, *gsq;
    cudaGetSymbolAddress((void**)&h1, g_h1);
    cudaGetSymbolAddress((void**)&h2, g_h2);
    cudaGetSymbolAddress((void**)&h3, g_h3);
    cudaGetSymbolAddress((void**)&gsum, g_sum);
    cudaGetSymbolAddress((void**)&gsq, g_sq);

    const int smem1 = 67*XSTR*4 + 67*64*4 + 2*64*4;   // 53,040 B -> 4 CTAs/SM
    const int smem2 = 64*XSTR*4 + 64*64*4 + 4*64*4;   // 51,200 B -> 4 CTAs/SM
    cudaFuncSetAttribute(gemm1_kernel, cudaFuncAttributeMaxDynamicSharedMemorySize, smem1);
    cudaFuncSetAttribute(gemm_bn_kernel<true>,  cudaFuncAttributeMaxDynamicSharedMemorySize, smem2);
    cudaFuncSetAttribute(gemm_bn_kernel<false>, cudaFuncAttributeMaxDynamicSharedMemorySize, smem2);

    // Launch order fixed so ncu (-s 5 -c 1) profiles launch #6 = layer-3 GEMM.
    zero_stats_kernel<<<1, 512>>>();                                   // 1
    ballquery_kernel<<<512, 256>>>(xyz, newxyz, 0);                    // 2
    ballquery_kernel<<<512, 256>>>(xyz, newxyz, 512);                  // 3

    gemm1_kernel<<<MROWS/128, 256, smem1>>>(xyz, points, newxyz, W1, b1,
                                            h1, gsum + 0, gsq + 0);    // 4

    gemm_bn_kernel<true><<<dim3(MROWS/128, 1), 256, smem2>>>(
        h1, W2, b2, ga1, be1, gsum + 0, gsq + 0,
        h2, 64, gsum + 128, gsq + 128);                                // 5

    gemm_bn_kernel<false><<<dim3(MROWS/128, 2), 256, smem2>>>(
        h2, W3, b3, ga2, be2, gsum + 128, gsq + 128,
        h3, 128, gsum + 256, gsq + 256);                               // 6 (profiled)

    maxpool_kernel<<<NQTOT, 128>>>(ga3, be3, outPts);                  // 7
}

// round 8
// speedup vs baseline: 1.8291x; 1.4807x over previous
#include <cuda_runtime.h>
#include <math.h>
#include <stdint.h>

// Problem constants (fixed shapes from the reference setup)
#define BQ    4
#define NP    16384
#define SQ    2048
#define KNN   32
#define NQTOT (BQ*SQ)          // 8192 query points
#define MROWS (NQTOT*KNN)      // 262144 grouped rows
#define RAD2  0.04f
#define BN_EPS 1e-5f
#define XSTR  132              // padded smem row stride (floats), 16B-aligned

typedef unsigned long long ULL;

// ---------------- scratch (device globals; no allocations allowed) ----------
__device__ int   g_idx[MROWS];
__device__ float g_h1[(size_t)64*MROWS];    // transposed [C][M]
__device__ float g_h2[(size_t)64*MROWS];    // transposed [C][M]
__device__ float g_h3[(size_t)MROWS*128];   // row-major  [M][C]
__device__ float g_sum[3*128];
__device__ float g_sq[3*128];

// ---------------- packed f32x2 helpers (bit-identical to 2x fmaf) -----------
__device__ __forceinline__ void fma2(ULL &d, ULL a, ULL b) {
    asm("fma.rn.f32x2 %0, %1, %2, %0;" : "+l"(d) : "l"(a), "l"(b));
}
__device__ __forceinline__ ULL pack2(float x) {
    ULL r;
    asm("mov.b64 %0, {%1, %1};" : "=l"(r) : "f"(x));
    return r;
}
__device__ __forceinline__ float2 unpack2(ULL v) {
    float2 r;
    asm("mov.b64 {%0, %1}, %2;" : "=f"(r.x), "=f"(r.y) : "l"(v));
    return r;
}

// ---------------- stats reset (graph replays re-run this) -------------------
__global__ void zero_stats_kernel() {
    int t = threadIdx.x + blockIdx.x * blockDim.x;
    if (t < 3*128) { g_sum[t] = 0.f; g_sq[t] = 0.f; }
}

// ---------------- ball query: warp per query, early exit --------------------
// FROZEN arithmetic: rounding pattern replicates the reference lowering.
__global__ void ballquery_kernel(const float* __restrict__ xyz,
                                 const float* __restrict__ newxyz,
                                 int blockOff) {
    int warp = (((blockIdx.x + blockOff) * blockDim.x) + threadIdx.x) >> 5;
    int lane = threadIdx.x & 31;
    if (warp >= NQTOT) return;
    int b = warp / SQ;
    const float* q = newxyz + (size_t)warp * 3;
    float qx = q[0], qy = q[1], qz = q[2];
    float qq = __fadd_rn(__fadd_rn(__fmul_rn(qx,qx), __fmul_rn(qy,qy)),
                         __fmul_rn(qz,qz));
    const float* xb = xyz + (size_t)b * NP * 3;
    int* outp = g_idx + (size_t)warp * KNN;
    int cnt = 0;
    int first = -1;
    for (int base = 0; base < NP; base += 32) {
        int p = base + lane;
        float x = xb[p*3+0], y = xb[p*3+1], z = xb[p*3+2];
        float xx = __fadd_rn(__fadd_rn(__fmul_rn(x,x), __fmul_rn(y,y)),
                             __fmul_rn(z,z));
        float dt = fmaf(qz, z, fmaf(qy, y, __fmul_rn(qx, x)));
        float d2 = __fsub_rn(__fadd_rn(qq, xx), __fmul_rn(2.0f, dt));
        bool hit = !(d2 > RAD2);
        unsigned mask = __ballot_sync(0xffffffffu, hit);
        if (mask) {
            if (first < 0) first = base + __ffs(mask) - 1;
            int pos = cnt + __popc(mask & ((1u << lane) - 1u));
            if (hit && pos < KNN) outp[pos] = p;
            cnt += __popc(mask);
            if (cnt >= KNN) break;
        }
    }
    if (cnt < KNN) {
        if (first < 0) first = 0;
        for (int pos = cnt + lane; pos < KNN; pos += 32) outp[pos] = first;
    }
}

// ---------------- f32x2 GEMM core: 8x8 outputs per thread -------------------
// Block = 128 threads = 16 (ti, rows) x 8 (tj, cols); tile = 128 rows x 64 cols.
// Thread (ti,tj) owns rows 8ti..8ti+7 x cols 8tj..8tj+7.
// X pairs come naturally (rows adjacent in smem); W is duplicated via mov.b64.
// acc[p][q] = (y[8ti+2p][8tj+q], y[8ti+2p+1][8tj+q]).
template<int CIN>
__device__ __forceinline__ void gemm_core8(const float* Xs, const float* Ws,
                                           ULL acc[4][8], int ti, int tj)
{
    const float* xp = Xs + 8*ti;
    const float* wp = Ws + 8*tj;
    #pragma unroll 4
    for (int c = 0; c < CIN; c++) {
        ulonglong2 xa = *reinterpret_cast<const ulonglong2*>(xp + c*XSTR);
        ulonglong2 xb = *reinterpret_cast<const ulonglong2*>(xp + c*XSTR + 4);
        float4 w0 = *reinterpret_cast<const float4*>(wp + c*64);
        float4 w1 = *reinterpret_cast<const float4*>(wp + c*64 + 4);
        ULL wd0 = pack2(w0.x), wd1 = pack2(w0.y);
        ULL wd2 = pack2(w0.z), wd3 = pack2(w0.w);
        ULL wd4 = pack2(w1.x), wd5 = pack2(w1.y);
        ULL wd6 = pack2(w1.z), wd7 = pack2(w1.w);
        fma2(acc[0][0], xa.x, wd0); fma2(acc[0][1], xa.x, wd1);
        fma2(acc[0][2], xa.x, wd2); fma2(acc[0][3], xa.x, wd3);
        fma2(acc[0][4], xa.x, wd4); fma2(acc[0][5], xa.x, wd5);
        fma2(acc[0][6], xa.x, wd6); fma2(acc[0][7], xa.x, wd7);
        fma2(acc[1][0], xa.y, wd0); fma2(acc[1][1], xa.y, wd1);
        fma2(acc[1][2], xa.y, wd2); fma2(acc[1][3], xa.y, wd3);
        fma2(acc[1][4], xa.y, wd4); fma2(acc[1][5], xa.y, wd5);
        fma2(acc[1][6], xa.y, wd6); fma2(acc[1][7], xa.y, wd7);
        fma2(acc[2][0], xb.x, wd0); fma2(acc[2][1], xb.x, wd1);
        fma2(acc[2][2], xb.x, wd2); fma2(acc[2][3], xb.x, wd3);
        fma2(acc[2][4], xb.x, wd4); fma2(acc[2][5], xb.x, wd5);
        fma2(acc[2][6], xb.x, wd6); fma2(acc[2][7], xb.x, wd7);
        fma2(acc[3][0], xb.y, wd0); fma2(acc[3][1], xb.y, wd1);
        fma2(acc[3][2], xb.y, wd2); fma2(acc[3][3], xb.y, wd3);
        fma2(acc[3][4], xb.y, wd4); fma2(acc[3][5], xb.y, wd5);
        fma2(acc[3][6], xb.y, wd6); fma2(acc[3][7], xb.y, wd7);
    }
}

// Epilogue. TRANS=true: Y is [C][MROWS] channel-major. Else row-major [M][COUTfull].
template<bool TRANS>
__device__ __forceinline__ void gemm_epilogue8(
    ULL acc[4][8], int m0, int ti, int tj, int t, int nOff, int COUTfull,
    const float* __restrict__ bias, float* __restrict__ Y,
    float* s_sum, float* s_sq,
    float* __restrict__ gsum, float* __restrict__ gsq)
{
    float bv[8];
    #pragma unroll
    for (int q = 0; q < 8; q++) bv[q] = bias[8*tj + q];

    float colSum[8], colSq[8];
    if (TRANS) {
        #pragma unroll
        for (int q = 0; q < 8; q++) {
            float2 a0 = unpack2(acc[0][q]);
            float2 a1 = unpack2(acc[1][q]);
            float2 a2 = unpack2(acc[2][q]);
            float2 a3 = unpack2(acc[3][q]);
            float v0 = a0.x + bv[q], v1 = a0.y + bv[q];
            float v2 = a1.x + bv[q], v3 = a1.y + bv[q];
            float v4 = a2.x + bv[q], v5 = a2.y + bv[q];
            float v6 = a3.x + bv[q], v7 = a3.y + bv[q];
            colSum[q] = ((v0+v1)+(v2+v3)) + ((v4+v5)+(v6+v7));
            float sq = 0.f;
            sq = fmaf(v0,v0,sq); sq = fmaf(v1,v1,sq);
            sq = fmaf(v2,v2,sq); sq = fmaf(v3,v3,sq);
            sq = fmaf(v4,v4,sq); sq = fmaf(v5,v5,sq);
            sq = fmaf(v6,v6,sq); sq = fmaf(v7,v7,sq);
            colSq[q] = sq;
            float* basep = Y + (size_t)(nOff + 8*tj + q) * MROWS + m0 + 8*ti;
            *reinterpret_cast<float4*>(basep)     = make_float4(v0, v1, v2, v3);
            *reinterpret_cast<float4*>(basep + 4) = make_float4(v4, v5, v6, v7);
        }
    } else {
        #pragma unroll
        for (int q = 0; q < 8; q++) { colSum[q] = 0.f; colSq[q] = 0.f; }
        #pragma unroll
        for (int p2 = 0; p2 < 8; p2++) {
            const int pp = p2 >> 1;
            float vals[8];
            #pragma unroll
            for (int q = 0; q < 8; q++) {
                float2 v = unpack2(acc[pp][q]);
                float a = ((p2 & 1) ? v.y : v.x) + bv[q];
                vals[q] = a;
                colSum[q] += a;
                colSq[q] = fmaf(a, a, colSq[q]);
            }
            float* d0 = Y + (size_t)(m0 + 8*ti + p2) * COUTfull + nOff + 8*tj;
            *reinterpret_cast<float4*>(d0)     = make_float4(vals[0], vals[1], vals[2], vals[3]);
            *reinterpret_cast<float4*>(d0 + 4) = make_float4(vals[4], vals[5], vals[6], vals[7]);
        }
    }
    #pragma unroll
    for (int q = 0; q < 8; q++) {
        atomicAdd(&s_sum[8*tj + q], colSum[q]);
        atomicAdd(&s_sq[8*tj + q],  colSq[q]);
    }
    __syncthreads();
    if (t < 64) {
        atomicAdd(&gsum[nOff + t], s_sum[t]);
        atomicAdd(&gsq[nOff + t],  s_sq[t]);
    }
}

// ---------------- layer 1: gather (ballquery idx) + GEMM 67->64 -------------
__global__ void __launch_bounds__(128, 4)
gemm1_kernel(const float* __restrict__ xyz,
             const float* __restrict__ points,
             const float* __restrict__ newxyz,
             const float* __restrict__ W,     // [64][67]
             const float* __restrict__ bias,
             float* __restrict__ Yt,          // [64][MROWS]
             float* __restrict__ gsum,
             float* __restrict__ gsq)
{
    constexpr int CIN = 67;
    extern __shared__ float sm[];
    float* Xs    = sm;                       // [67][XSTR]
    float* Ws    = sm + CIN*XSTR;            // [67][64]
    float* s_sum = Ws + CIN*64;
    float* s_sq  = s_sum + 64;
    const int t  = threadIdx.x;
    const int ti = t >> 3;                   // 0..15
    const int tj = t & 7;                    // 0..7
    const int m0 = blockIdx.x * 128;

    for (int i = t; i < 64*CIN; i += 128) {
        int o = i / CIN, c = i - o*CIN;
        Ws[c*64 + o] = W[i];
    }
    if (t < 64) { s_sum[t] = 0.f; s_sq[t] = 0.f; }

    {   // coalesced gather: 16 lanes cover 16 consecutive 16B chunks of a row
        const int k  = t & 15;               // chunk 0..15 (channels 3+4k..6+4k)
        const int rb = t >> 4;               // 0..7
        #pragma unroll
        for (int it = 0; it < 16; it++) {
            const int r = rb + it*8;
            const int m = m0 + r;
            const int b = m >> 16;
            const int j = g_idx[m];
            float4 x = *(reinterpret_cast<const float4*>(
                             points + (size_t)(b*NP + j) * 64) + k);
            const int c = 3 + 4*k;
            Xs[(c+0)*XSTR + r] = x.x;
            Xs[(c+1)*XSTR + r] = x.y;
            Xs[(c+2)*XSTR + r] = x.z;
            Xs[(c+3)*XSTR + r] = x.w;
            if (k == 0) {
                const int s = (m >> 5) & (SQ - 1);
                const float* pj = xyz    + (size_t)(b*NP + j) * 3;
                const float* qv = newxyz + (size_t)(b*SQ + s) * 3;
                Xs[0*XSTR + r] = pj[0] - qv[0];
                Xs[1*XSTR + r] = pj[1] - qv[1];
                Xs[2*XSTR + r] = pj[2] - qv[2];
            }
        }
    }
    __syncthreads();

    ULL acc[4][8];
    #pragma unroll
    for (int p = 0; p < 4; p++)
        #pragma unroll
        for (int q = 0; q < 8; q++) acc[p][q] = 0ull;

    gemm_core8<CIN>(Xs, Ws, acc, ti, tj);
    gemm_epilogue8<true>(acc, m0, ti, tj, t, 0, 64, bias, Yt, s_sum, s_sq, gsum, gsq);
}

// ---------------- layers 2/3: BN+ReLU(prev) folded, transposed input --------
template<bool TRANS>
__global__ void __launch_bounds__(128, 4)
gemm_bn_kernel(const float* __restrict__ Xt,   // [64][MROWS]
               const float* __restrict__ W,    // [COUTtot][64]
               const float* __restrict__ bias,
               const float* __restrict__ gammaP,
               const float* __restrict__ betaP,
               const float* __restrict__ gsumP,
               const float* __restrict__ gsqP,
               float* __restrict__ Y,
               int COUTfull,
               float* __restrict__ gsum,
               float* __restrict__ gsq)
{
    constexpr int CIN = 64;
    extern __shared__ float sm[];
    float* Xs    = sm;                       // [64][XSTR]
    float* Ws    = sm + CIN*XSTR;            // [64][64]
    float* s_sum = Ws + CIN*64;
    float* s_sq  = s_sum + 64;
    float* sscl  = s_sq + 64;
    float* sshf  = sscl + 64;
    const int t    = threadIdx.x;
    const int lane = t & 31;
    const int warp = t >> 5;                 // 0..3
    const int ti   = t >> 3;
    const int tj   = t & 7;
    const int m0   = blockIdx.x * 128;
    const int nOff = blockIdx.y * 64;

    const float* Wblk = W + (size_t)nOff * CIN;
    for (int i = t; i < 64*CIN; i += 128) {
        int o = i >> 6, c = i & 63;
        Ws[c*64 + o] = Wblk[i];
    }
    if (t < 64) {
        s_sum[t] = 0.f; s_sq[t] = 0.f;
        // inline finalize of previous layer's BN (identical arithmetic)
        const float invM = 1.0f / (float)MROWS;
        float mean = gsumP[t] * invM;
        float var  = gsqP[t] * invM - mean*mean;
        float rs = rsqrtf(var + BN_EPS);
        float sc = gammaP[t] * rs;
        sscl[t] = sc;
        sshf[t] = betaP[t] - mean*sc;
    }
    __syncthreads();

    {   // warp-per-channel contiguous load (512B/instr) + BN + ReLU
        #pragma unroll
        for (int i = 0; i < 16; i++) {
            const int c = warp*16 + i;
            const float sc = sscl[c], sh = sshf[c];
            float4 x = *reinterpret_cast<const float4*>(
                Xt + (size_t)c*MROWS + m0 + 4*lane);
            float4 o;
            o.x = fmaxf(fmaf(x.x, sc, sh), 0.f);
            o.y = fmaxf(fmaf(x.y, sc, sh), 0.f);
            o.z = fmaxf(fmaf(x.z, sc, sh), 0.f);
            o.w = fmaxf(fmaf(x.w, sc, sh), 0.f);
            *reinterpret_cast<float4*>(Xs + c*XSTR + 4*lane) = o;
        }
    }
    __syncthreads();

    ULL acc[4][8];
    #pragma unroll
    for (int p = 0; p < 4; p++)
        #pragma unroll
        for (int q = 0; q < 8; q++) acc[p][q] = 0ull;

    gemm_core8<CIN>(Xs, Ws, acc, ti, tj);
    gemm_epilogue8<TRANS>(acc, m0, ti, tj, t, nOff, COUTfull,
                          bias + nOff, Y, s_sum, s_sq, gsum, gsq);
}

// ---------------- BN3 + ReLU + max over K + transpose -----------------------
__global__ void maxpool_kernel(const float* __restrict__ gamma,
                               const float* __restrict__ beta,
                               float* __restrict__ out)
{
    const int q = blockIdx.x;      // b*SQ + s
    const int o = threadIdx.x;     // channel 0..127
    const int b = q / SQ, s = q - b*SQ;
    const float invM = 1.0f / (float)MROWS;
    float mean = g_sum[2*128 + o] * invM;
    float var  = g_sq[2*128 + o] * invM - mean*mean;
    float rs = rsqrtf(var + BN_EPS);
    float sc = gamma[o] * rs;
    float sh = beta[o] - mean*sc;
    const float* h = g_h3 + (size_t)q * KNN * 128 + o;
    float mx = -3.402823466e38f;
    #pragma unroll
    for (int k = 0; k < KNN; k++)
        mx = fmaxf(mx, fmaf(h[(size_t)k*128], sc, sh));
    out[(size_t)(b*128 + o) * SQ + s] = fmaxf(mx, 0.f);
}

// ---------------- launch ------------------------------------------------
extern "C" void kernel_launch(void* const* d_in, const int* in_sizes, int n_in,
                              void* d_out, int out_size) {
    const float* xyz    = (const float*)d_in[0];
    const float* points = (const float*)d_in[1];
    const float* newxyz = (const float*)d_in[2];
    const float* W1 = (const float*)d_in[3],  *b1 = (const float*)d_in[4];
    const float* ga1 = (const float*)d_in[5], *be1 = (const float*)d_in[6];
    const float* W2 = (const float*)d_in[7],  *b2 = (const float*)d_in[8];
    const float* ga2 = (const float*)d_in[9], *be2 = (const float*)d_in[10];
    const float* W3 = (const float*)d_in[11], *b3 = (const float*)d_in[12];
    const float* ga3 = (const float*)d_in[13], *be3 = (const float*)d_in[14];

    float* out = (float*)d_out;
    float* outPts = out;
    if (out_size == BQ*SQ*3 + BQ*128*SQ) {
        cudaMemcpyAsync(out, newxyz, sizeof(float)*BQ*SQ*3, cudaMemcpyDeviceToDevice);
        outPts = out + BQ*SQ*3;
    }

    float *h1, *h2, *h3, *gsum, *gsq;
    cudaGetSymbolAddress((void**)&h1, g_h1);
    cudaGetSymbolAddress((void**)&h2, g_h2);
    cudaGetSymbolAddress((void**)&h3, g_h3);
    cudaGetSymbolAddress((void**)&gsum, g_sum);
    cudaGetSymbolAddress((void**)&gsq, g_sq);

    const int smem1 = 67*XSTR*4 + 67*64*4 + 2*64*4;   // 53,040 B -> 4 CTAs/SM
    const int smem2 = 64*XSTR*4 + 64*64*4 + 4*64*4;   // 51,200 B -> 4 CTAs/SM
    cudaFuncSetAttribute(gemm1_kernel, cudaFuncAttributeMaxDynamicSharedMemorySize, smem1);
    cudaFuncSetAttribute(gemm_bn_kernel<true>,  cudaFuncAttributeMaxDynamicSharedMemorySize, smem2);
    cudaFuncSetAttribute(gemm_bn_kernel<false>, cudaFuncAttributeMaxDynamicSharedMemorySize, smem2);

    // Launch order fixed so ncu (-s 5 -c 1) profiles launch #6 = layer-3 GEMM.
    zero_stats_kernel<<<1, 512>>>();                                   // 1
    ballquery_kernel<<<512, 256>>>(xyz, newxyz, 0);                    // 2
    ballquery_kernel<<<512, 256>>>(xyz, newxyz, 512);                  // 3

    gemm1_kernel<<<MROWS/128, 128, smem1>>>(xyz, points, newxyz, W1, b1,
                                            h1, gsum + 0, gsq + 0);    // 4

    gemm_bn_kernel<true><<<dim3(MROWS/128, 1), 128, smem2>>>(
        h1, W2, b2, ga1, be1, gsum + 0, gsq + 0,
        h2, 64, gsum + 128, gsq + 128);                                // 5

    gemm_bn_kernel<false><<<dim3(MROWS/128, 2), 128, smem2>>>(
        h2, W3, b3, ga2, be2, gsum + 128, gsq + 128,
        h3, 128, gsum + 256, gsq + 256);                               // 6 (profiled)

    maxpool_kernel<<<NQTOT, 128>>>(ga3, be3, outPts);                  // 7
}

// round 9
// speedup vs baseline: 2.2682x; 1.2401x over previous
#include <cuda_runtime.h>
#include <math.h>
#include <stdint.h>

// Problem constants (fixed shapes from the reference setup)
#define BQ    4
#define NP    16384
#define SQ    2048
#define KNN   32
#define NQTOT (BQ*SQ)          // 8192 query points
#define MROWS (NQTOT*KNN)      // 262144 grouped rows
#define RAD2  0.04f
#define BN_EPS 1e-5f
#define XSTR  132              // padded smem row stride (floats), 16B-aligned

typedef unsigned long long ULL;

// ---------------- scratch (device globals; no allocations allowed) ----------
__device__ int   g_idx[MROWS];
__device__ float g_h1[(size_t)64*MROWS];    // transposed [C][M]
__device__ float g_h2[(size_t)64*MROWS];    // transposed [C][M]
__device__ float g_h3[(size_t)MROWS*128];   // row-major  [M][C]
__device__ float g_sum[3*128];
__device__ float g_sq[3*128];

// ---------------- packed f32x2 helpers (bit-identical to 2x fmaf) -----------
__device__ __forceinline__ void fma2(ULL &d, ULL a, ULL b) {
    asm("fma.rn.f32x2 %0, %1, %2, %0;" : "+l"(d) : "l"(a), "l"(b));
}
__device__ __forceinline__ ULL pack2(float x) {
    ULL r;
    asm("mov.b64 %0, {%1, %1};" : "=l"(r) : "f"(x));
    return r;
}
__device__ __forceinline__ float2 unpack2(ULL v) {
    float2 r;
    asm("mov.b64 {%0, %1}, %2;" : "=f"(r.x), "=f"(r.y) : "l"(v));
    return r;
}

// W slot interleave: thread tj reads float4s at slots tj and 8+tj so that a
// warp's 8 concurrent W loads cover all 32 banks (1 wavefront instead of 2).
// Output column o lives at float offset wslot(o) within a 64-float W row.
__device__ __forceinline__ int wslot(int o) {
    return ((o & 4) << 3) + ((o >> 3) << 2) + (o & 3);
}
// X row swizzle vs channel quad: physical row = r ^ xsw(c) (4-aligned XOR).
__device__ __forceinline__ int xsw(int c) {
    return ((c >> 2) & 7) << 2;
}

// ---------------- stats reset (graph replays re-run this) -------------------
__global__ void zero_stats_kernel() {
    int t = threadIdx.x + blockIdx.x * blockDim.x;
    if (t < 3*128) { g_sum[t] = 0.f; g_sq[t] = 0.f; }
}

// ---------------- ball query: warp per query, early exit --------------------
// FROZEN arithmetic: rounding pattern replicates the reference lowering.
__global__ void ballquery_kernel(const float* __restrict__ xyz,
                                 const float* __restrict__ newxyz,
                                 int blockOff) {
    int warp = (((blockIdx.x + blockOff) * blockDim.x) + threadIdx.x) >> 5;
    int lane = threadIdx.x & 31;
    if (warp >= NQTOT) return;
    int b = warp / SQ;
    const float* q = newxyz + (size_t)warp * 3;
    float qx = q[0], qy = q[1], qz = q[2];
    float qq = __fadd_rn(__fadd_rn(__fmul_rn(qx,qx), __fmul_rn(qy,qy)),
                         __fmul_rn(qz,qz));
    const float* xb = xyz + (size_t)b * NP * 3;
    int* outp = g_idx + (size_t)warp * KNN;
    int cnt = 0;
    int first = -1;
    for (int base = 0; base < NP; base += 32) {
        int p = base + lane;
        float x = xb[p*3+0], y = xb[p*3+1], z = xb[p*3+2];
        float xx = __fadd_rn(__fadd_rn(__fmul_rn(x,x), __fmul_rn(y,y)),
                             __fmul_rn(z,z));
        float dt = fmaf(qz, z, fmaf(qy, y, __fmul_rn(qx, x)));
        float d2 = __fsub_rn(__fadd_rn(qq, xx), __fmul_rn(2.0f, dt));
        bool hit = !(d2 > RAD2);
        unsigned mask = __ballot_sync(0xffffffffu, hit);
        if (mask) {
            if (first < 0) first = base + __ffs(mask) - 1;
            int pos = cnt + __popc(mask & ((1u << lane) - 1u));
            if (hit && pos < KNN) outp[pos] = p;
            cnt += __popc(mask);
            if (cnt >= KNN) break;
        }
    }
    if (cnt < KNN) {
        if (first < 0) first = 0;
        for (int pos = cnt + lane; pos < KNN; pos += 32) outp[pos] = first;
    }
}

// ---------------- one k-step: 2 X loads + 2 W loads + 32 FFMA2 --------------
__device__ __forceinline__ void k_step(const float* Xs, const float* wp,
                                       ULL acc[4][8], int aA, int aB, int c)
{
    ulonglong2 xa = *reinterpret_cast<const ulonglong2*>(Xs + c*XSTR + aA);
    ulonglong2 xb = *reinterpret_cast<const ulonglong2*>(Xs + c*XSTR + aB);
    float4 w0 = *reinterpret_cast<const float4*>(wp + c*64);
    float4 w1 = *reinterpret_cast<const float4*>(wp + c*64 + 32);
    ULL wd0 = pack2(w0.x), wd1 = pack2(w0.y);
    ULL wd2 = pack2(w0.z), wd3 = pack2(w0.w);
    ULL wd4 = pack2(w1.x), wd5 = pack2(w1.y);
    ULL wd6 = pack2(w1.z), wd7 = pack2(w1.w);
    fma2(acc[0][0], xa.x, wd0); fma2(acc[0][1], xa.x, wd1);
    fma2(acc[0][2], xa.x, wd2); fma2(acc[0][3], xa.x, wd3);
    fma2(acc[0][4], xa.x, wd4); fma2(acc[0][5], xa.x, wd5);
    fma2(acc[0][6], xa.x, wd6); fma2(acc[0][7], xa.x, wd7);
    fma2(acc[1][0], xa.y, wd0); fma2(acc[1][1], xa.y, wd1);
    fma2(acc[1][2], xa.y, wd2); fma2(acc[1][3], xa.y, wd3);
    fma2(acc[1][4], xa.y, wd4); fma2(acc[1][5], xa.y, wd5);
    fma2(acc[1][6], xa.y, wd6); fma2(acc[1][7], xa.y, wd7);
    fma2(acc[2][0], xb.x, wd0); fma2(acc[2][1], xb.x, wd1);
    fma2(acc[2][2], xb.x, wd2); fma2(acc[2][3], xb.x, wd3);
    fma2(acc[2][4], xb.x, wd4); fma2(acc[2][5], xb.x, wd5);
    fma2(acc[2][6], xb.x, wd6); fma2(acc[2][7], xb.x, wd7);
    fma2(acc[3][0], xb.y, wd0); fma2(acc[3][1], xb.y, wd1);
    fma2(acc[3][2], xb.y, wd2); fma2(acc[3][3], xb.y, wd3);
    fma2(acc[3][4], xb.y, wd4); fma2(acc[3][5], xb.y, wd5);
    fma2(acc[3][6], xb.y, wd6); fma2(acc[3][7], xb.y, wd7);
}

// ---------------- f32x2 GEMM core: 8x8 outputs per thread -------------------
// Block = 128 threads = 16 (ti) x 8 (tj); tile = 128 rows x 64 cols.
// X rows swizzled by channel quad; W slots interleaved (see wslot/xsw).
template<int CIN>
__device__ __forceinline__ void gemm_core8(const float* Xs, const float* Ws,
                                           ULL acc[4][8], int ti, int tj)
{
    const int rowA = 8*ti;
    const float* wp = Ws + 4*tj;
    #pragma unroll 2
    for (int b = 0; b < CIN/4; b++) {
        const int sw = (b & 7) << 2;
        const int aA = rowA ^ sw;
        const int aB = aA ^ 4;
        #pragma unroll
        for (int u = 0; u < 4; u++)
            k_step(Xs, wp, acc, aA, aB, 4*b + u);
    }
    #pragma unroll
    for (int c = (CIN & ~3); c < CIN; c++)     // tail quad has sw == 0
        k_step(Xs, wp, acc, rowA, rowA + 4, c);
}

// Epilogue. TRANS=true: Y is [C][MROWS] channel-major. Else row-major [M][COUTfull].
template<bool TRANS>
__device__ __forceinline__ void gemm_epilogue8(
    ULL acc[4][8], int m0, int ti, int tj, int t, int nOff, int COUTfull,
    const float* __restrict__ bias, float* __restrict__ Y,
    float* s_sum, float* s_sq,
    float* __restrict__ gsum, float* __restrict__ gsq)
{
    float bv[8];
    #pragma unroll
    for (int q = 0; q < 8; q++) bv[q] = bias[8*tj + q];

    float colSum[8], colSq[8];
    if (TRANS) {
        #pragma unroll
        for (int q = 0; q < 8; q++) {
            float2 a0 = unpack2(acc[0][q]);
            float2 a1 = unpack2(acc[1][q]);
            float2 a2 = unpack2(acc[2][q]);
            float2 a3 = unpack2(acc[3][q]);
            float v0 = a0.x + bv[q], v1 = a0.y + bv[q];
            float v2 = a1.x + bv[q], v3 = a1.y + bv[q];
            float v4 = a2.x + bv[q], v5 = a2.y + bv[q];
            float v6 = a3.x + bv[q], v7 = a3.y + bv[q];
            colSum[q] = ((v0+v1)+(v2+v3)) + ((v4+v5)+(v6+v7));
            float sq = 0.f;
            sq = fmaf(v0,v0,sq); sq = fmaf(v1,v1,sq);
            sq = fmaf(v2,v2,sq); sq = fmaf(v3,v3,sq);
            sq = fmaf(v4,v4,sq); sq = fmaf(v5,v5,sq);
            sq = fmaf(v6,v6,sq); sq = fmaf(v7,v7,sq);
            colSq[q] = sq;
            float* basep = Y + (size_t)(nOff + 8*tj + q) * MROWS + m0 + 8*ti;
            *reinterpret_cast<float4*>(basep)     = make_float4(v0, v1, v2, v3);
            *reinterpret_cast<float4*>(basep + 4) = make_float4(v4, v5, v6, v7);
        }
    } else {
        #pragma unroll
        for (int q = 0; q < 8; q++) { colSum[q] = 0.f; colSq[q] = 0.f; }
        #pragma unroll
        for (int p2 = 0; p2 < 8; p2++) {
            const int pp = p2 >> 1;
            float vals[8];
            #pragma unroll
            for (int q = 0; q < 8; q++) {
                float2 v = unpack2(acc[pp][q]);
                float a = ((p2 & 1) ? v.y : v.x) + bv[q];
                vals[q] = a;
                colSum[q] += a;
                colSq[q] = fmaf(a, a, colSq[q]);
            }
            float* d0 = Y + (size_t)(m0 + 8*ti + p2) * COUTfull + nOff + 8*tj;
            *reinterpret_cast<float4*>(d0)     = make_float4(vals[0], vals[1], vals[2], vals[3]);
            *reinterpret_cast<float4*>(d0 + 4) = make_float4(vals[4], vals[5], vals[6], vals[7]);
        }
    }
    // warp pre-reduction across the 4 ti-groups sharing a tj (lanes 8 apart),
    // then one conflict-free smem atomic per (warp, column).
    const unsigned FULL = 0xffffffffu;
    #pragma unroll
    for (int q = 0; q < 8; q++) {
        float s1 = colSum[q];
        s1 += __shfl_xor_sync(FULL, s1, 8);
        s1 += __shfl_xor_sync(FULL, s1, 16);
        float s2 = colSq[q];
        s2 += __shfl_xor_sync(FULL, s2, 8);
        s2 += __shfl_xor_sync(FULL, s2, 16);
        if ((t & 31) < 8) {
            atomicAdd(&s_sum[8*tj + q], s1);
            atomicAdd(&s_sq[8*tj + q],  s2);
        }
    }
    __syncthreads();
    if (t < 64) {
        atomicAdd(&gsum[nOff + t], s_sum[t]);
        atomicAdd(&gsq[nOff + t],  s_sq[t]);
    }
}

// ---------------- layer 1: gather (ballquery idx) + GEMM 67->64 -------------
__global__ void __launch_bounds__(128, 3)
gemm1_kernel(const float* __restrict__ xyz,
             const float* __restrict__ points,
             const float* __restrict__ newxyz,
             const float* __restrict__ W,     // [64][67]
             const float* __restrict__ bias,
             float* __restrict__ Yt,          // [64][MROWS]
             float* __restrict__ gsum,
             float* __restrict__ gsq)
{
    constexpr int CIN = 67;
    extern __shared__ float sm[];
    float* Xs    = sm;                       // [67][XSTR], rows swizzled
    float* Ws    = sm + CIN*XSTR;            // [67][64], slots interleaved
    float* s_sum = Ws + CIN*64;
    float* s_sq  = s_sum + 64;
    const int t  = threadIdx.x;
    const int ti = t >> 3;                   // 0..15
    const int tj = t & 7;                    // 0..7
    const int m0 = blockIdx.x * 128;

    for (int i = t; i < 64*CIN; i += 128) {
        int o = i / CIN, c = i - o*CIN;
        Ws[c*64 + wslot(o)] = W[i];
    }
    if (t < 64) { s_sum[t] = 0.f; s_sq[t] = 0.f; }

    {   // coalesced gather; swizzled STS (2-way worst-case conflicts)
        const int k  = t & 15;               // chunk 0..15 (channels 3+4k..6+4k)
        const int rb = t >> 4;               // 0..7
        const int sw0 = (k & 7) << 2;        // quad of channel 3+4k
        const int sw1 = ((k+1) & 7) << 2;    // quad of channels 4+4k..6+4k
        #pragma unroll
        for (int it = 0; it < 16; it++) {
            const int r = rb + it*8;
            const int m = m0 + r;
            const int b = m >> 16;
            const int j = g_idx[m];
            float4 x = *(reinterpret_cast<const float4*>(
                             points + (size_t)(b*NP + j) * 64) + k);
            const int c = 3 + 4*k;
            Xs[(c+0)*XSTR + (r ^ sw0)] = x.x;
            Xs[(c+1)*XSTR + (r ^ sw1)] = x.y;
            Xs[(c+2)*XSTR + (r ^ sw1)] = x.z;
            Xs[(c+3)*XSTR + (r ^ sw1)] = x.w;
            if (k == 0) {   // channels 0..2 are quad 0 -> sw = 0
                const int s = (m >> 5) & (SQ - 1);
                const float* pj = xyz    + (size_t)(b*NP + j) * 3;
                const float* qv = newxyz + (size_t)(b*SQ + s) * 3;
                Xs[0*XSTR + r] = pj[0] - qv[0];
                Xs[1*XSTR + r] = pj[1] - qv[1];
                Xs[2*XSTR + r] = pj[2] - qv[2];
            }
        }
    }
    __syncthreads();

    ULL acc[4][8];
    #pragma unroll
    for (int p = 0; p < 4; p++)
        #pragma unroll
        for (int q = 0; q < 8; q++) acc[p][q] = 0ull;

    gemm_core8<CIN>(Xs, Ws, acc, ti, tj);
    gemm_epilogue8<true>(acc, m0, ti, tj, t, 0, 64, bias, Yt, s_sum, s_sq, gsum, gsq);
}

// ---------------- layers 2/3: BN+ReLU(prev) folded, transposed input --------
template<bool TRANS>
__global__ void __launch_bounds__(128, 3)
gemm_bn_kernel(const float* __restrict__ Xt,   // [64][MROWS]
               const float* __restrict__ W,    // [COUTtot][64]
               const float* __restrict__ bias,
               const float* __restrict__ gammaP,
               const float* __restrict__ betaP,
               const float* __restrict__ gsumP,
               const float* __restrict__ gsqP,
               float* __restrict__ Y,
               int COUTfull,
               float* __restrict__ gsum,
               float* __restrict__ gsq)
{
    constexpr int CIN = 64;
    extern __shared__ float sm[];
    float* Xs    = sm;                       // [64][XSTR], rows swizzled
    float* Ws    = sm + CIN*XSTR;            // [64][64], slots interleaved
    float* s_sum = Ws + CIN*64;
    float* s_sq  = s_sum + 64;
    float* sscl  = s_sq + 64;
    float* sshf  = sscl + 64;
    const int t    = threadIdx.x;
    const int lane = t & 31;
    const int warp = t >> 5;                 // 0..3
    const int ti   = t >> 3;
    const int tj   = t & 7;
    const int m0   = blockIdx.x * 128;
    const int nOff = blockIdx.y * 64;

    const float* Wblk = W + (size_t)nOff * CIN;
    for (int i = t; i < 64*CIN; i += 128) {
        int o = i >> 6, c = i & 63;
        Ws[c*64 + wslot(o)] = Wblk[i];
    }
    if (t < 64) {
        s_sum[t] = 0.f; s_sq[t] = 0.f;
        // inline finalize of previous layer's BN (identical arithmetic)
        const float invM = 1.0f / (float)MROWS;
        float mean = gsumP[t] * invM;
        float var  = gsqP[t] * invM - mean*mean;
        float rs = rsqrtf(var + BN_EPS);
        float sc = gammaP[t] * rs;
        sscl[t] = sc;
        sshf[t] = betaP[t] - mean*sc;
    }
    __syncthreads();

    {   // warp-per-channel contiguous load (512B/instr) + BN + ReLU
        #pragma unroll
        for (int i = 0; i < 16; i++) {
            const int c = warp*16 + i;
            const float sc = sscl[c], sh = sshf[c];
            float4 x = *reinterpret_cast<const float4*>(
                Xt + (size_t)c*MROWS + m0 + 4*lane);
            float4 o;
            o.x = fmaxf(fmaf(x.x, sc, sh), 0.f);
            o.y = fmaxf(fmaf(x.y, sc, sh), 0.f);
            o.z = fmaxf(fmaf(x.z, sc, sh), 0.f);
            o.w = fmaxf(fmaf(x.w, sc, sh), 0.f);
            *reinterpret_cast<float4*>(Xs + c*XSTR + ((4*lane) ^ xsw(c))) = o;
        }
    }
    __syncthreads();

    ULL acc[4][8];
    #pragma unroll
    for (int p = 0; p < 4; p++)
        #pragma unroll
        for (int q = 0; q < 8; q++) acc[p][q] = 0ull;

    gemm_core8<CIN>(Xs, Ws, acc, ti, tj);
    gemm_epilogue8<TRANS>(acc, m0, ti, tj, t, nOff, COUTfull,
                          bias + nOff, Y, s_sum, s_sq, gsum, gsq);
}

// ---------------- BN3 + ReLU + max over K + transpose -----------------------
__global__ void maxpool_kernel(const float* __restrict__ gamma,
                               const float* __restrict__ beta,
                               float* __restrict__ out)
{
    const int q = blockIdx.x;      // b*SQ + s
    const int o = threadIdx.x;     // channel 0..127
    const int b = q / SQ, s = q - b*SQ;
    const float invM = 1.0f / (float)MROWS;
    float mean = g_sum[2*128 + o] * invM;
    float var  = g_sq[2*128 + o] * invM - mean*mean;
    float rs = rsqrtf(var + BN_EPS);
    float sc = gamma[o] * rs;
    float sh = beta[o] - mean*sc;
    const float* h = g_h3 + (size_t)q * KNN * 128 + o;
    float mx = -3.402823466e38f;
    #pragma unroll
    for (int k = 0; k < KNN; k++)
        mx = fmaxf(mx, fmaf(h[(size_t)k*128], sc, sh));
    out[(size_t)(b*128 + o) * SQ + s] = fmaxf(mx, 0.f);
}

// ---------------- launch ------------------------------------------------
extern "C" void kernel_launch(void* const* d_in, const int* in_sizes, int n_in,
                              void* d_out, int out_size) {
    const float* xyz    = (const float*)d_in[0];
    const float* points = (const float*)d_in[1];
    const float* newxyz = (const float*)d_in[2];
    const float* W1 = (const float*)d_in[3],  *b1 = (const float*)d_in[4];
    const float* ga1 = (const float*)d_in[5], *be1 = (const float*)d_in[6];
    const float* W2 = (const float*)d_in[7],  *b2 = (const float*)d_in[8];
    const float* ga2 = (const float*)d_in[9], *be2 = (const float*)d_in[10];
    const float* W3 = (const float*)d_in[11], *b3 = (const float*)d_in[12];
    const float* ga3 = (const float*)d_in[13], *be3 = (const float*)d_in[14];

    float* out = (float*)d_out;
    float* outPts = out;
    if (out_size == BQ*SQ*3 + BQ*128*SQ) {
        cudaMemcpyAsync(out, newxyz, sizeof(float)*BQ*SQ*3, cudaMemcpyDeviceToDevice);
        outPts = out + BQ*SQ*3;
    }

    float *h1, *h2, *h3, *gsum, *gsq;
    cudaGetSymbolAddress((void**)&h1, g_h1);
    cudaGetSymbolAddress((void**)&h2, g_h2);
    cudaGetSymbolAddress((void**)&h3, g_h3);
    cudaGetSymbolAddress((void**)&gsum, g_sum);
    cudaGetSymbolAddress((void**)&gsq, g_sq);

    const int smem1 = 67*XSTR*4 + 67*64*4 + 2*64*4;   // 53,040 B
    const int smem2 = 64*XSTR*4 + 64*64*4 + 4*64*4;   // 51,200 B
    cudaFuncSetAttribute(gemm1_kernel, cudaFuncAttributeMaxDynamicSharedMemorySize, smem1);
    cudaFuncSetAttribute(gemm_bn_kernel<true>,  cudaFuncAttributeMaxDynamicSharedMemorySize, smem2);
    cudaFuncSetAttribute(gemm_bn_kernel<false>, cudaFuncAttributeMaxDynamicSharedMemorySize, smem2);

    // Launch order fixed so ncu (-s 5 -c 1) profiles launch #6 = layer-3 GEMM.
    zero_stats_kernel<<<1, 512>>>();                                   // 1
    ballquery_kernel<<<512, 256>>>(xyz, newxyz, 0);                    // 2
    ballquery_kernel<<<512, 256>>>(xyz, newxyz, 512);                  // 3

    gemm1_kernel<<<MROWS/128, 128, smem1>>>(xyz, points, newxyz, W1, b1,
                                            h1, gsum + 0, gsq + 0);    // 4

    gemm_bn_kernel<true><<<dim3(MROWS/128, 1), 128, smem2>>>(
        h1, W2, b2, ga1, be1, gsum + 0, gsq + 0,
        h2, 64, gsum + 128, gsq + 128);                                // 5

    gemm_bn_kernel<false><<<dim3(MROWS/128, 2), 128, smem2>>>(
        h2, W3, b3, ga2, be2, gsum + 128, gsq + 128,
        h3, 128, gsum + 256, gsq + 256);                               // 6 (profiled)

    maxpool_kernel<<<NQTOT, 128>>>(ga3, be3, outPts);                  // 7
}